// round 9
// baseline (speedup 1.0000x reference)
#include <cuda_runtime.h>
#include <cstddef>

// DilatedKNN: B=4, N=8192, C=64, K=9, dilation=2 -> top-18 nearest, take ::2.
// Output dtype is FLOAT32 (confirmed round 8): indices written as floats.
//
// Numerics deliberately MATCH the reference formula:
//   d2 = |s|^2 + |q|^2 - 2*dot(s,q)  in fp32, key = max(d2, 0)
// (sqrt is monotone -> dropped). Norms use one shared sequential-fmaf routine
// so query/support norms of the same row are bit-identical; stable strict-'<'
// insertion reproduces jax.lax.top_k tie-breaking (smaller index first).

#define BATCH 4
#define NPTS  8192
#define CDIM  64
#define KOUT  9
#define KK    18      // K_NEIGHBORS * DILATION
#define TS    128     // support tile rows cached in smem
#define TPB   128     // threads per block = query rows per block

__global__ void __launch_bounds__(TPB)
knn_kernel(const float* __restrict__ q, float* __restrict__ out) {
    const int b = blockIdx.x >> 6;                       // 64 blocks per batch
    const int m = ((blockIdx.x & 63) << 7) + threadIdx.x;
    const float* qb = q + (size_t)b * NPTS * CDIM;

    __shared__ __align__(16) float sT[TS * CDIM];   // 32 KB support tile
    __shared__ float sS[TS];                        // tile squared norms

    // Query row in registers (scalar coalesced-enough loads; tiny cost).
    float qv[CDIM];
    {
        const float* qr = qb + (size_t)m * CDIM;
#pragma unroll
        for (int c = 0; c < CDIM; c++) qv[c] = qr[c];
    }
    // Query norm: sequential fmaf (same routine as support norms below).
    float sqm = 0.f;
#pragma unroll
    for (int c = 0; c < CDIM; c++) sqm = fmaf(qv[c], qv[c], sqm);

    // Sorted ascending top-KK; strict '<' keeps earlier index on ties.
    float kd[KK];
    int   ki[KK];
#pragma unroll
    for (int j = 0; j < KK; j++) { kd[j] = 3.402823466e38f; ki[j] = 0; }

    for (int s0 = 0; s0 < NPTS; s0 += TS) {
        __syncthreads();   // previous tile fully consumed
        {
            // Cooperative tile load: TS*CDIM floats over TPB threads.
            const float* src = qb + (size_t)s0 * CDIM;
#pragma unroll
            for (int i = 0; i < (TS * CDIM) / TPB; i++) {
                int idx = threadIdx.x + i * TPB;
                sT[idx] = src[idx];
            }
        }
        __syncthreads();   // tile visible
        {
            // Support row norms: sequential fmaf — identical routine to sqm,
            // so norm(row) is bit-equal whether row is query or support.
            const float* row = sT + threadIdx.x * CDIM;
            float s = 0.f;
#pragma unroll
            for (int c = 0; c < CDIM; c++) s = fmaf(row[c], row[c], s);
            sS[threadIdx.x] = s;
        }
        __syncthreads();   // norms visible

#pragma unroll 2
        for (int s = 0; s < TS; s++) {
            const float4* srow = (const float4*)(sT + s * CDIM);  // 16B-mult offset
            // Dot product, 8 independent FMA chains for ILP.
            float a0 = 0.f, a1 = 0.f, a2 = 0.f, a3 = 0.f;
            float a4 = 0.f, a5 = 0.f, a6 = 0.f, a7 = 0.f;
#pragma unroll
            for (int i = 0; i < CDIM / 8; i++) {
                float4 v0 = srow[2 * i];
                float4 v1 = srow[2 * i + 1];
                a0 = fmaf(qv[8 * i + 0], v0.x, a0);
                a1 = fmaf(qv[8 * i + 1], v0.y, a1);
                a2 = fmaf(qv[8 * i + 2], v0.z, a2);
                a3 = fmaf(qv[8 * i + 3], v0.w, a3);
                a4 = fmaf(qv[8 * i + 4], v1.x, a4);
                a5 = fmaf(qv[8 * i + 5], v1.y, a5);
                a6 = fmaf(qv[8 * i + 6], v1.z, a6);
                a7 = fmaf(qv[8 * i + 7], v1.w, a7);
            }
            float dot = ((a0 + a1) + (a2 + a3)) + ((a4 + a5) + (a6 + a7));
            // Reference formula order: (sq_s + sq_q) - 2*dot. 2*dot is exact
            // (power-of-two scale), so one rounding on the subtract.
            float t   = sS[s] + sqm;
            float d2  = t - 2.0f * dot;
            float key = fmaxf(d2, 0.0f);       // == ranking by sqrt(max(d2,0))
            if (key < kd[KK - 1]) {
                kd[KK - 1] = key;
                ki[KK - 1] = s0 + s;
#pragma unroll
                for (int j = KK - 1; j >= 1; --j) {
                    if (kd[j] < kd[j - 1]) {
                        float tk = kd[j]; kd[j] = kd[j - 1]; kd[j - 1] = tk;
                        int   ti = ki[j]; ki[j] = ki[j - 1]; ki[j - 1] = ti;
                    }
                }
            }
        }
    }

    // Dilated slice ::2 of the sorted top-18, written as float32.
    float* orow = out + ((size_t)(b * NPTS + m)) * KOUT;
#pragma unroll
    for (int j = 0; j < KOUT; j++) orow[j] = (float)ki[2 * j];
}

// ---------------------------------------------------------------------------
extern "C" void kernel_launch(void* const* d_in, const int* in_sizes, int n_in,
                              void* d_out, int out_size) {
    const float* q = (const float*)d_in[0];
    float* out = (float*)d_out;
    knn_kernel<<<BATCH * (NPTS / TPB), TPB>>>(q, out);
}

// round 10
// speedup vs baseline: 1.2204x; 1.2204x over previous
#include <cuda_runtime.h>
#include <cstddef>

// DilatedKNN: B=4, N=8192, C=64, K=9, d=2 -> top-18 nearest, slice ::2.
// Output dtype float32 (confirmed R8/R9). Numerics match reference formula:
//   key = max((|s|^2 + |q|^2) - 2*dot, 0), sequential-fmaf norms.
//
// R10: GEMM-style register tiling. R9 ncu: L1=51% vs fma=26% -> LDS-bound
// (16 LDS.128 per 64 FFMA). Now 8 queries x 8 candidates per thread:
// 256 FFMA per 16 LDS.128 (4x less LDS/FMA), dot matrix transposed through
// smem so top-k scan reads 1 float/candidate instead of 64.

#define BATCH 4
#define NPTS  8192
#define CDIM  64
#define KOUT  9
#define KK    18
#define MQ    128     // queries per block
#define TSC   64      // candidate tile rows
#define TPB   128

// dynamic smem layout (floats):
//   q4  : MQ  x 16 float4  (swizzled)  = 8192 floats
//   s4  : TSC x 16 float4  (swizzled)  = 4096 floats
//   d2s : MQ x 65                      = 8320 floats
//   sS  : TSC                          =   64 floats
#define SM_Q4   0
#define SM_S4   8192
#define SM_D2   (8192 + 4096)
#define SM_SS   (SM_D2 + MQ * 65)
#define SM_FLOATS (SM_SS + TSC)

__global__ void __launch_bounds__(TPB)
knn_kernel(const float* __restrict__ q, float* __restrict__ out) {
    extern __shared__ float smem[];
    float4* q4  = (float4*)(smem + SM_Q4);
    float4* s4  = (float4*)(smem + SM_S4);
    float*  d2s = smem + SM_D2;
    float*  sS  = smem + SM_SS;

    const int b  = blockIdx.x >> 6;              // 64 blocks per batch
    const int q0 = (blockIdx.x & 63) * MQ;       // base query row
    const float* qb = q + (size_t)b * NPTS * CDIM;
    const int tid = threadIdx.x;
    const int ty  = tid >> 3;                    // 0..15 -> queries ty+16j
    const int tx  = tid & 7;                     // 0..7  -> candidates tx+8c

    // ---- load query tile, XOR-swizzled by row low bits ----
    for (int i = tid; i < MQ * 16; i += TPB) {
        int r = i >> 4, kc = i & 15;
        float4 v = ((const float4*)(qb + (size_t)(q0 + r) * CDIM))[kc];
        q4[(r << 4) + (kc ^ (r & 15))] = v;
    }
    __syncthreads();

    // my query norm: sequential fmaf over k (same routine as support norms)
    float sqm = 0.f;
#pragma unroll
    for (int kc = 0; kc < 16; kc++) {
        float4 v = q4[(tid << 4) + (kc ^ (tid & 15))];
        sqm = fmaf(v.x, v.x, sqm); sqm = fmaf(v.y, v.y, sqm);
        sqm = fmaf(v.z, v.z, sqm); sqm = fmaf(v.w, v.w, sqm);
    }

    // top-18, ascending; strict '<' = stable ties (jax.lax.top_k)
    float kd[KK];
    int   ki[KK];
#pragma unroll
    for (int j = 0; j < KK; j++) { kd[j] = 3.402823466e38f; ki[j] = 0; }

    for (int c0 = 0; c0 < NPTS; c0 += TSC) {
        // ---- load candidate tile (prev phase-B reads only d2s/sS: no hazard) ----
        for (int i = tid; i < TSC * 16; i += TPB) {
            int r = i >> 4, kc = i & 15;
            float4 v = ((const float4*)(qb + (size_t)(c0 + r) * CDIM))[kc];
            s4[(r << 4) + (kc ^ (r & 15))] = v;
        }
        __syncthreads();   // tile ready; also: all threads past prev phase B

        // support norms (threads < TSC), identical sequential-fmaf order
        if (tid < TSC) {
            float s = 0.f;
#pragma unroll
            for (int kc = 0; kc < 16; kc++) {
                float4 v = s4[(tid << 4) + (kc ^ (tid & 15))];
                s = fmaf(v.x, v.x, s); s = fmaf(v.y, v.y, s);
                s = fmaf(v.z, v.z, s); s = fmaf(v.w, v.w, s);
            }
            sS[tid] = s;
        }

        // ---- phase A: 8x8 register-tiled dot products ----
        float acc[8][8];
#pragma unroll
        for (int j = 0; j < 8; j++)
#pragma unroll
            for (int c = 0; c < 8; c++) acc[j][c] = 0.f;

#pragma unroll 4
        for (int kc = 0; kc < 16; kc++) {
            float4 qf[8], sf[8];
#pragma unroll
            for (int j = 0; j < 8; j++)           // qi = ty+16j, qi&15 == ty
                qf[j] = q4[((ty + (j << 4)) << 4) + (kc ^ ty)];
#pragma unroll
            for (int c = 0; c < 8; c++) {
                int sj = tx + (c << 3);
                sf[c] = s4[(sj << 4) + (kc ^ (sj & 15))];
            }
#pragma unroll
            for (int j = 0; j < 8; j++)
#pragma unroll
                for (int c = 0; c < 8; c++) {
                    acc[j][c] = fmaf(qf[j].x, sf[c].x, acc[j][c]);
                    acc[j][c] = fmaf(qf[j].y, sf[c].y, acc[j][c]);
                    acc[j][c] = fmaf(qf[j].z, sf[c].z, acc[j][c]);
                    acc[j][c] = fmaf(qf[j].w, sf[c].w, acc[j][c]);
                }
        }

        // transpose dots through smem (stride 65: conflict-free phase B)
#pragma unroll
        for (int j = 0; j < 8; j++)
#pragma unroll
            for (int c = 0; c < 8; c++)
                d2s[(ty + (j << 4)) * 65 + tx + (c << 3)] = acc[j][c];
        __syncthreads();   // dots + norms visible

        // ---- phase B: scan my query's 64 dots, insert top-18 ----
        const float* row = d2s + tid * 65;
#pragma unroll 4
        for (int s = 0; s < TSC; s++) {
            float t   = sS[s] + sqm;
            float d2  = t - 2.0f * row[s];        // reference formula order
            float key = fmaxf(d2, 0.0f);
            if (key < kd[KK - 1]) {
                kd[KK - 1] = key;
                ki[KK - 1] = c0 + s;
#pragma unroll
                for (int j = KK - 1; j >= 1; --j) {
                    if (kd[j] < kd[j - 1]) {
                        float tk = kd[j]; kd[j] = kd[j - 1]; kd[j - 1] = tk;
                        int   ti = ki[j]; ki[j] = ki[j - 1]; ki[j - 1] = ti;
                    }
                }
            }
        }
    }

    // dilated slice ::2 of sorted top-18, as float32
    float* orow = out + ((size_t)(b * NPTS + q0 + tid)) * KOUT;
#pragma unroll
    for (int j = 0; j < KOUT; j++) orow[j] = (float)ki[2 * j];
}

// ---------------------------------------------------------------------------
extern "C" void kernel_launch(void* const* d_in, const int* in_sizes, int n_in,
                              void* d_out, int out_size) {
    const float* q = (const float*)d_in[0];
    float* out = (float*)d_out;
    size_t smem_bytes = (size_t)SM_FLOATS * sizeof(float);   // ~82.7 KB
    cudaFuncSetAttribute(knn_kernel,
                         cudaFuncAttributeMaxDynamicSharedMemorySize,
                         (int)smem_bytes);
    knn_kernel<<<BATCH * (NPTS / MQ), TPB, smem_bytes>>>(q, out);
}

// round 11
// speedup vs baseline: 1.2767x; 1.0461x over previous
#include <cuda_runtime.h>
#include <cstddef>

// DilatedKNN: B=4, N=8192, C=64, K=9, d=2 -> top-18 nearest, slice ::2.
// Output float32 (confirmed). key = max((|s|^2+|q|^2) - 2*dot, 0).
//
// R11: (1) padded k-major smem layouts -> immediate-offset LDS (kills the
// 31.7% alu pipe from XOR swizzles); (2) fma.rn.f32x2 with (even,odd) row
// pairing + pre-swapped candidate copy -> 2048 packed FMA/tile vs 4096 FFMA,
// zero pack movs. Dot/norm accumulation order bit-identical to R10.

#define BATCH 4
#define NPTS  8192
#define CDIM  64
#define KOUT  9
#define KK    18
#define MQ    128     // queries per block
#define TSC   64      // candidate tile rows
#define TPB   128
#define NK2   32      // k2 steps (2 k per step)

// smem layout (floats):
//  qsm : 32 k2 x 65 quads (64 qpairs + pad)          = 8320 floats
//  U   : union region, 8448 floats:
//        phase A: ssm 32x33 quads (4224) + ssw (4224)
//        phase B: d2s 128 x 66                        (8448)
//  sS  : 64 floats
#define SM_U      8320
#define SM_SSW    (SM_U + 4224)
#define SM_SS     (SM_U + 8448)
#define SM_FLOATS (SM_SS + 64)

__device__ __forceinline__ void fma2(unsigned long long& d,
                                     unsigned long long a,
                                     unsigned long long b) {
    asm("fma.rn.f32x2 %0, %1, %2, %0;" : "+l"(d) : "l"(a), "l"(b));
}
__device__ __forceinline__ float2 unpack2(unsigned long long v) {
    float2 r;
    asm("mov.b64 {%0, %1}, %2;" : "=f"(r.x), "=f"(r.y) : "l"(v));
    return r;
}

__global__ void __launch_bounds__(TPB)
knn_kernel(const float* __restrict__ q, float* __restrict__ out) {
    extern __shared__ float smem[];
    float4*     qsm4 = (float4*)smem;                    // [k2*65 + p]
    ulonglong2* qsmU = (ulonglong2*)smem;
    float4*     ssm4 = (float4*)(smem + SM_U);           // [k2*33 + p]
    ulonglong2* ssmU = (ulonglong2*)(smem + SM_U);
    float4*     ssw4 = (float4*)(smem + SM_SSW);
    ulonglong2* sswU = (ulonglong2*)(smem + SM_SSW);
    float*      d2s  = smem + SM_U;                      // aliases ssm/ssw
    float*      sS   = smem + SM_SS;

    const int b  = blockIdx.x >> 6;
    const int q0 = (blockIdx.x & 63) * MQ;
    const float* qb = q + (size_t)b * NPTS * CDIM;
    const int tid = threadIdx.x;
    const int ty  = tid >> 3;   // 0..15: qpairs ty+16*jp
    const int tx  = tid & 7;    // 0..7 : cpairs tx+8*cp

    // ---- load query tile, pair-interleaved k-major ----
    for (int t = tid; t < 64 * 16; t += TPB) {
        int p = t >> 4, kc = t & 15;
        float4 a = ((const float4*)(qb + (size_t)(q0 + 2 * p) * CDIM))[kc];
        float4 c = ((const float4*)(qb + (size_t)(q0 + 2 * p + 1) * CDIM))[kc];
        qsm4[(2 * kc) * 65 + p]     = make_float4(a.x, c.x, a.y, c.y);
        qsm4[(2 * kc + 1) * 65 + p] = make_float4(a.z, c.z, a.w, c.w);
    }
    __syncthreads();

    // my query norm (query row = tid): sequential fmaf over k
    float sqm = 0.f;
    {
        int p = tid >> 1, e = tid & 1;
#pragma unroll
        for (int k2 = 0; k2 < NK2; k2++) {
            float4 v = qsm4[k2 * 65 + p];
            float f0 = e ? v.y : v.x;
            float f1 = e ? v.w : v.z;
            sqm = fmaf(f0, f0, sqm);
            sqm = fmaf(f1, f1, sqm);
        }
    }

    float kd[KK];
    int   ki[KK];
#pragma unroll
    for (int j = 0; j < KK; j++) { kd[j] = 3.402823466e38f; ki[j] = 0; }

    for (int c0 = 0; c0 < NPTS; c0 += TSC) {
        __syncthreads();   // prev phase B done -> safe to overwrite union
        // ---- load candidate tile + swapped copy ----
        for (int t = tid; t < 32 * 16; t += TPB) {
            int p = t >> 4, kc = t & 15;
            float4 a = ((const float4*)(qb + (size_t)(c0 + 2 * p) * CDIM))[kc];
            float4 c = ((const float4*)(qb + (size_t)(c0 + 2 * p + 1) * CDIM))[kc];
            ssm4[(2 * kc) * 33 + p]     = make_float4(a.x, c.x, a.y, c.y);
            ssm4[(2 * kc + 1) * 33 + p] = make_float4(a.z, c.z, a.w, c.w);
            ssw4[(2 * kc) * 33 + p]     = make_float4(c.x, a.x, c.y, a.y);
            ssw4[(2 * kc + 1) * 33 + p] = make_float4(c.z, a.z, c.w, a.w);
        }
        __syncthreads();

        // support norms (rows 0..63), same sequential-fmaf order
        if (tid < TSC) {
            int p = tid >> 1, e = tid & 1;
            float s = 0.f;
#pragma unroll
            for (int k2 = 0; k2 < NK2; k2++) {
                float4 v = ssm4[k2 * 33 + p];
                float f0 = e ? v.y : v.x;
                float f1 = e ? v.w : v.z;
                s = fmaf(f0, f0, s);
                s = fmaf(f1, f1, s);
            }
            sS[tid] = s;
        }

        // ---- phase A: packed 8x8 via f32x2 ----
        unsigned long long accA[4][4], accB[4][4];
#pragma unroll
        for (int jp = 0; jp < 4; jp++)
#pragma unroll
            for (int cp = 0; cp < 4; cp++) { accA[jp][cp] = 0ull; accB[jp][cp] = 0ull; }

#pragma unroll 4
        for (int k2 = 0; k2 < NK2; k2++) {
            ulonglong2 qv[4], sv[4], wv[4];
#pragma unroll
            for (int jp = 0; jp < 4; jp++) qv[jp] = qsmU[k2 * 65 + ty + 16 * jp];
#pragma unroll
            for (int cp = 0; cp < 4; cp++) {
                sv[cp] = ssmU[k2 * 33 + tx + 8 * cp];
                wv[cp] = sswU[k2 * 33 + tx + 8 * cp];
            }
#pragma unroll
            for (int jp = 0; jp < 4; jp++)
#pragma unroll
                for (int cp = 0; cp < 4; cp++) {
                    fma2(accA[jp][cp], qv[jp].x, sv[cp].x);  // k   : (qe*se, qo*so)
                    fma2(accA[jp][cp], qv[jp].y, sv[cp].y);  // k+1
                    fma2(accB[jp][cp], qv[jp].x, wv[cp].x);  // k   : (qe*so, qo*se)
                    fma2(accB[jp][cp], qv[jp].y, wv[cp].y);  // k+1
                }
        }
        __syncthreads();   // all reads of ssm/ssw done; union becomes d2s

        // ---- transpose dots into d2s[q*66 + c] (float2 stores, aligned) ----
#pragma unroll
        for (int jp = 0; jp < 4; jp++)
#pragma unroll
            for (int cp = 0; cp < 4; cp++) {
                float2 A = unpack2(accA[jp][cp]);   // (qe.se, qo.so)
                float2 Bv = unpack2(accB[jp][cp]);  // (qe.so, qo.se)
                int qe = 2 * (ty + 16 * jp);
                int ce = 2 * (tx + 8 * cp);
                *(float2*)(d2s + qe * 66 + ce)       = make_float2(A.x, Bv.x);
                *(float2*)(d2s + (qe + 1) * 66 + ce) = make_float2(Bv.y, A.y);
            }
        __syncthreads();   // dots + norms visible

        // ---- phase B: scan my query's 64 dots ----
        const float* row = d2s + tid * 66;
#pragma unroll 4
        for (int s = 0; s < TSC; s++) {
            float t   = sS[s] + sqm;
            float d2  = t - 2.0f * row[s];
            float key = fmaxf(d2, 0.0f);
            if (key < kd[KK - 1]) {
                kd[KK - 1] = key;
                ki[KK - 1] = c0 + s;
#pragma unroll
                for (int j = KK - 1; j >= 1; --j) {
                    if (kd[j] < kd[j - 1]) {
                        float tk = kd[j]; kd[j] = kd[j - 1]; kd[j - 1] = tk;
                        int   ti = ki[j]; ki[j] = ki[j - 1]; ki[j - 1] = ti;
                    }
                }
            }
        }
    }

    float* orow = out + ((size_t)(b * NPTS + q0 + tid)) * KOUT;
#pragma unroll
    for (int j = 0; j < KOUT; j++) orow[j] = (float)ki[2 * j];
}

// ---------------------------------------------------------------------------
extern "C" void kernel_launch(void* const* d_in, const int* in_sizes, int n_in,
                              void* d_out, int out_size) {
    const float* q = (const float*)d_in[0];
    float* out = (float*)d_out;
    size_t smem_bytes = (size_t)SM_FLOATS * sizeof(float);   // ~67.3 KB
    cudaFuncSetAttribute(knn_kernel,
                         cudaFuncAttributeMaxDynamicSharedMemorySize,
                         (int)smem_bytes);
    knn_kernel<<<BATCH * (NPTS / MQ), TPB, smem_bytes>>>(q, out);
}